// round 4
// baseline (speedup 1.0000x reference)
#include <cuda_runtime.h>
#include <cuda_bf16.h>
#include <cstdint>

#define NROWS 8192
#define KDIM  128
#define GAMMA_F 0.005f   // 1/(2*10^2)

#define TILE 128
#define THREADS 256

// SMEM: padded bf16 tiles, row stride 272 bytes (128 bf16 = 256B + 16B pad)
#define ROW_BYTES 272
#define TILE_BYTES (TILE * ROW_BYTES)          // 34816
#define SMEM_A  0
#define SMEM_B  TILE_BYTES                      // 34816
#define SMEM_N1 (2 * TILE_BYTES)                // 69632
#define SMEM_N2 (SMEM_N1 + TILE * 4)            // 70144
#define SMEM_TOTAL (SMEM_N2 + TILE * 4)         // 70656

__device__ float g_n1[NROWS];
__device__ float g_n2[NROWS];

static __device__ __forceinline__ uint32_t smem_u32(const void* p) {
    uint32_t a;
    asm("{ .reg .u64 t; cvta.to.shared.u64 t, %1; cvt.u32.u64 %0, t; }"
        : "=r"(a) : "l"(p));
    return a;
}

static __device__ __forceinline__ void ldsm_x4(uint32_t& r0, uint32_t& r1,
                                               uint32_t& r2, uint32_t& r3,
                                               uint32_t addr) {
    asm volatile("ldmatrix.sync.aligned.m8n8.x4.shared.b16 {%0,%1,%2,%3}, [%4];"
                 : "=r"(r0), "=r"(r1), "=r"(r2), "=r"(r3) : "r"(addr));
}

static __device__ __forceinline__ void mma_16816(float* d,
                                                 const uint32_t* a,
                                                 uint32_t b0, uint32_t b1) {
    asm volatile(
        "mma.sync.aligned.m16n8k16.row.col.f32.bf16.bf16.f32 "
        "{%0,%1,%2,%3}, {%4,%5,%6,%7}, {%8,%9}, {%0,%1,%2,%3};"
        : "+f"(d[0]), "+f"(d[1]), "+f"(d[2]), "+f"(d[3])
        : "r"(a[0]), "r"(a[1]), "r"(a[2]), "r"(a[3]), "r"(b0), "r"(b1));
}

// ---------------- norms kernel ----------------
__global__ void rbf_norms_kernel(const float* __restrict__ x1,
                                 const float* __restrict__ x2)
{
    int warp = (blockIdx.x * blockDim.x + threadIdx.x) >> 5;
    int lane = threadIdx.x & 31;
    if (warp >= 2 * NROWS) return;
    const float* src = (warp < NROWS) ? x1 : x2;
    float* dst = (warp < NROWS) ? g_n1 : g_n2;
    int row = warp & (NROWS - 1);
    float4 v = reinterpret_cast<const float4*>(src + (size_t)row * KDIM)[lane];
    float s = v.x * v.x + v.y * v.y + v.z * v.z + v.w * v.w;
    #pragma unroll
    for (int m = 16; m > 0; m >>= 1)
        s += __shfl_xor_sync(0xFFFFFFFFu, s, m);
    if (lane == 0) dst[row] = s;
}

// ---------------- main kernel ----------------
__global__ void __launch_bounds__(THREADS)
rbf_mma_kernel(const float* __restrict__ x1,
               const float* __restrict__ x2,
               float* __restrict__ out)
{
    extern __shared__ char smem[];
    uint32_t sbase = smem_u32(smem);
    int tid = threadIdx.x;
    int wid = tid >> 5;
    int lane = tid & 31;

    int rowBase = blockIdx.y * TILE;
    int colBase = blockIdx.x * TILE;

    // ---- load tiles fp32 -> bf16 into padded SMEM + stage norms ----
    {
        const float4* a4 = reinterpret_cast<const float4*>(x1 + (size_t)rowBase * KDIM);
        const float4* b4 = reinterpret_cast<const float4*>(x2 + (size_t)colBase * KDIM);
        #pragma unroll
        for (int it = 0; it < (TILE * 32) / THREADS; ++it) {
            int idx = tid + it * THREADS;   // 0..4095
            int row = idx >> 5;
            int c4  = idx & 31;             // float4 index within row
            float4 va = a4[(size_t)row * 32 + c4];
            float4 vb = b4[(size_t)row * 32 + c4];
            __nv_bfloat162 a0 = __floats2bfloat162_rn(va.x, va.y);
            __nv_bfloat162 a1 = __floats2bfloat162_rn(va.z, va.w);
            __nv_bfloat162 b0 = __floats2bfloat162_rn(vb.x, vb.y);
            __nv_bfloat162 b1 = __floats2bfloat162_rn(vb.z, vb.w);
            uint32_t off = (uint32_t)row * ROW_BYTES + (uint32_t)c4 * 8;
            *reinterpret_cast<uint2*>(smem + SMEM_A + off) =
                make_uint2(*reinterpret_cast<uint32_t*>(&a0), *reinterpret_cast<uint32_t*>(&a1));
            *reinterpret_cast<uint2*>(smem + SMEM_B + off) =
                make_uint2(*reinterpret_cast<uint32_t*>(&b0), *reinterpret_cast<uint32_t*>(&b1));
        }
        if (tid < TILE) {
            reinterpret_cast<float*>(smem + SMEM_N1)[tid] = g_n1[rowBase + tid];
        } else {
            reinterpret_cast<float*>(smem + SMEM_N2)[tid - TILE] = g_n2[colBase + (tid - TILE)];
        }
    }
    __syncthreads();

    // ---- mma mainloop: warp grid 2(M) x 4(N); each warp 64x32 ----
    int mw = wid >> 2;       // 0..1
    int nw = wid & 3;        // 0..3

    float acc[4][4][4];      // [mi][ni][reg]
    #pragma unroll
    for (int mi = 0; mi < 4; ++mi)
        #pragma unroll
        for (int ni = 0; ni < 4; ++ni)
            #pragma unroll
            for (int r = 0; r < 4; ++r) acc[mi][ni][r] = 0.0f;

    // ldmatrix address components (row = lane%16, k-half = lane/16)
    uint32_t lrow  = lane & 15;
    uint32_t lhalf = (lane >> 4) * 16;   // byte offset of k-half

    #pragma unroll
    for (int ks = 0; ks < 8; ++ks) {
        uint32_t koff = (uint32_t)ks * 32 + lhalf;

        uint32_t af[4][4];
        #pragma unroll
        for (int mi = 0; mi < 4; ++mi) {
            uint32_t row = (uint32_t)(mw * 64 + mi * 16) + lrow;
            ldsm_x4(af[mi][0], af[mi][1], af[mi][2], af[mi][3],
                    sbase + SMEM_A + row * ROW_BYTES + koff);
        }
        uint32_t bf[2][4];
        #pragma unroll
        for (int nj = 0; nj < 2; ++nj) {
            uint32_t row = (uint32_t)(nw * 32 + nj * 16) + lrow;
            ldsm_x4(bf[nj][0], bf[nj][1], bf[nj][2], bf[nj][3],
                    sbase + SMEM_B + row * ROW_BYTES + koff);
        }
        #pragma unroll
        for (int mi = 0; mi < 4; ++mi) {
            #pragma unroll
            for (int ni = 0; ni < 4; ++ni) {
                int nj = ni >> 1, sub = ni & 1;
                mma_16816(acc[mi][ni], af[mi], bf[nj][sub], bf[nj][sub + 2]);
            }
        }
    }
    __syncthreads();

    // ---- fused RBF epilogue ----
    {
        const float* sn1 = reinterpret_cast<const float*>(smem + SMEM_N1);
        const float* sn2 = reinterpret_cast<const float*>(smem + SMEM_N2);
        int qr = lane >> 2;          // 0..7
        int qc = (lane & 3) * 2;     // 0,2,4,6

        #pragma unroll
        for (int mi = 0; mi < 4; ++mi) {
            int row0 = mw * 64 + mi * 16 + qr;       // rows row0 and row0+8
            float n1a = sn1[row0];
            float n1b = sn1[row0 + 8];
            float* out0 = out + (size_t)(rowBase + row0) * NROWS + colBase;
            float* out1 = out0 + (size_t)8 * NROWS;
            #pragma unroll
            for (int ni = 0; ni < 4; ++ni) {
                int col = nw * 32 + ni * 8 + qc;
                float n2a = sn2[col];
                float n2b = sn2[col + 1];
                float2 oa, ob;
                oa.x = __expf(-GAMMA_F * (n1a + n2a - 2.0f * acc[mi][ni][0]));
                oa.y = __expf(-GAMMA_F * (n1a + n2b - 2.0f * acc[mi][ni][1]));
                ob.x = __expf(-GAMMA_F * (n1b + n2a - 2.0f * acc[mi][ni][2]));
                ob.y = __expf(-GAMMA_F * (n1b + n2b - 2.0f * acc[mi][ni][3]));
                *reinterpret_cast<float2*>(out0 + col) = oa;
                *reinterpret_cast<float2*>(out1 + col) = ob;
            }
        }
    }
}

// ---------------- launch ----------------
extern "C" void kernel_launch(void* const* d_in, const int* in_sizes, int n_in,
                              void* d_out, int out_size)
{
    const float* x1 = (const float*)d_in[0];
    const float* x2 = (const float*)d_in[1];
    float* out = (float*)d_out;

    cudaFuncSetAttribute(rbf_mma_kernel,
                         cudaFuncAttributeMaxDynamicSharedMemorySize, SMEM_TOTAL);

    rbf_norms_kernel<<<(2 * NROWS) / 8, 256>>>(x1, x2);

    dim3 grid(NROWS / TILE, NROWS / TILE);   // 64 x 64
    rbf_mma_kernel<<<grid, THREADS, SMEM_TOTAL>>>(x1, x2, out);
}